// round 16
// baseline (speedup 1.0000x reference)
#include <cuda_runtime.h>
#include <cuda_bf16.h>
#include <mma.h>
#include <cstdint>
using namespace nvcuda;

#define B_  8
#define N_  2048
#define M_  2048
#define DP_ 128
#define DM_ 256
#define K_  16
#define BN_  (B_*N_)        // 16384
#define BNK_ (B_*N_*K_)     // 262144
#define GPD 148             // persistent grid size

typedef __nv_bfloat16 bf16;
typedef __nv_bfloat162 bf162;

// ---------------- scratch (device globals: allocation-free rule) -------------
__device__ bf16  g_featb [BN_*DP_];
__device__ bf16  g_featsb[BN_*DP_];
__device__ bf16  g_qb [BN_*DM_];
__device__ bf16  g_xsb[BN_*DM_];
__device__ bf16  g_kb [BN_*DM_];
__device__ bf16  g_vb [BN_*DM_];
__device__ bf16  g_gb [(size_t)BNK_*DM_];   // g
__device__ bf16  g_hb [(size_t)BNK_*DM_];   // relu(g@fg1+b)
__device__ bf16  g_vpb[(size_t)BNK_*DM_];   // vg + pos
__device__ bf16  g_resb[BN_*DM_];
__device__ float g_outtmp[BN_*DP_];
__device__ int   g_knn [BNK_];
__device__ float g_zerobias[DM_];           // zero-initialized

// bf16 weight copies (row-major, same layout as fp32 originals)
__device__ bf16 g_w_fc1 [DP_*DM_];
__device__ bf16 g_w_fc1s[DP_*DM_];
__device__ bf16 g_w_wk  [DM_*DM_];
__device__ bf16 g_w_wv  [DM_*DM_];
__device__ bf16 g_w_fd2 [DM_*DM_];
__device__ bf16 g_w_fg1 [DM_*DM_];
__device__ bf16 g_w_fg2 [DM_*DM_];
__device__ bf16 g_w_fc2 [DM_*DP_];

// ---------------- cp.async helpers -------------------------------------------
__device__ __forceinline__ unsigned saddr(const void* p) {
    return (unsigned)__cvta_generic_to_shared(p);
}
__device__ __forceinline__ void cpa16(unsigned dst, const void* src) {
    asm volatile("cp.async.cg.shared.global [%0], [%1], 16;\n" :: "r"(dst), "l"(src));
}
#define CP_COMMIT()  asm volatile("cp.async.commit_group;\n")
#define CP_WAIT1()   asm volatile("cp.async.wait_group 1;\n")
#define CP_WAIT0()   asm volatile("cp.async.wait_group 0;\n")

// ---------------- fused fp32 -> bf16 convert ---------------------------------
struct CvtArgs { const float* s[10]; bf16* d[10]; };
#define CVT_TOTAL 4620288LL
#define CVT_BLOCKS 9024

__global__ void __launch_bounds__(256) cvtall_k(CvtArgs a)
{
    const long long cum[11] = {0LL, 2097152LL, 4194304LL, 4227072LL, 4259840LL,
                               4325376LL, 4390912LL, 4456448LL, 4521984LL,
                               4587520LL, 4620288LL};
    long long p = ((long long)blockIdx.x * 256 + threadIdx.x) * 2;
    if (p >= CVT_TOTAL) return;
    int seg = 0;
    #pragma unroll
    for (int s = 1; s < 10; s++) if (p >= cum[s]) seg = s;
    long long off = p - cum[seg];
    float2 v = *reinterpret_cast<const float2*>(a.s[seg] + off);
    *reinterpret_cast<bf162*>(a.d[seg] + off) = __float22bfloat162_rn(v);
}

// ---------------- KNN: exact expanded-form d2, stable top-16 -----------------
__global__ void __launch_bounds__(128) knn_k(const float* __restrict__ xyz,
                                             const float* __restrict__ xyzs)
{
    __shared__ float sy0[M_], sy1[M_], sy2[M_], syn[M_];
    int b = blockIdx.x;
    int n = blockIdx.y * 128 + threadIdx.x;
    const float* ys = xyzs + (size_t)b * M_ * 3;
    for (int m = threadIdx.x; m < M_; m += 128) {
        float y0 = ys[m*3+0], y1 = ys[m*3+1], y2 = ys[m*3+2];
        sy0[m] = y0; sy1[m] = y1; sy2[m] = y2;
        syn[m] = __fadd_rn(__fadd_rn(__fmul_rn(y0,y0), __fmul_rn(y1,y1)), __fmul_rn(y2,y2));
    }
    __syncthreads();

    const float* x = xyz + ((size_t)b * N_ + n) * 3;
    float x0 = x[0], x1 = x[1], x2 = x[2];
    float xn = __fadd_rn(__fadd_rn(__fmul_rn(x0,x0), __fmul_rn(x1,x1)), __fmul_rn(x2,x2));

    float bd[K_]; int bi[K_];
    #pragma unroll
    for (int k = 0; k < K_; k++) { bd[k] = 3.4e38f; bi[k] = 0; }

    for (int m = 0; m < M_; m++) {
        float dot = __fadd_rn(__fadd_rn(__fmul_rn(x0, sy0[m]), __fmul_rn(x1, sy1[m])),
                              __fmul_rn(x2, sy2[m]));
        float d2 = __fsub_rn(__fadd_rn(xn, syn[m]), __fmul_rn(2.0f, dot));
        if (d2 < bd[K_-1]) {
            int p = K_ - 1;
            while (p > 0 && bd[p-1] > d2) { bd[p] = bd[p-1]; bi[p] = bi[p-1]; p--; }
            bd[p] = d2; bi[p] = m;
        }
    }
    size_t base = ((size_t)b * N_ + n) * K_;
    #pragma unroll
    for (int k = 0; k < K_; k++) g_knn[base + k] = bi[k];
}

// ======= persistent bf16 wmma GEMM: B resident in SMEM, A 3-stage ring =======
// smem: Bres[KD][BNT+8] | As[3][128][40] | Cs[8][16][20]
#define HGP_SMEM(KD,BNT) ((KD)*((BNT)+8)*2 + 30720 + 10240)

template<int KD, int BNT, bool RELU, bool ADDSRC, bool OUTBF>
__global__ void __launch_bounds__(256, 1)
hgemm_pk(const bf16* __restrict__ A,
         const bf16* __restrict__ W,
         const float* __restrict__ bias,
         const float* __restrict__ Add,   // fp32 add source (stride BNT)
         void* __restrict__ Cout, int ntiles)
{
    extern __shared__ __align__(16) char smem[];
    constexpr int SB  = BNT + 8;
    constexpr int NK  = KD / 32;
    constexpr int WRN = (BNT == 256) ? 4 : 2;
    bf16* Bres = (bf16*)smem;
    typedef bf16 (*AsT)[128][40];
    AsT As = (AsT)(smem + KD*SB*2);
    float (*Cs)[16][20] = (float(*)[16][20])(smem + KD*SB*2 + 30720);

    int bid = blockIdx.x, G = gridDim.x;
    int tid = threadIdx.x;
    int wid = tid >> 5, lane = tid & 31;
    int wr = (BNT == 256) ? (wid >> 2) * 64 : (wid >> 1) * 32;
    int wc = (BNT == 256) ? (wid & 3) * 64 : (wid & 1) * 64;

    if (bid >= ntiles) return;
    int nloc  = (ntiles - bid + G - 1) / G;
    int Slast = nloc * NK - 1;

    // ---- load resident B (once) ----
    #pragma unroll
    for (int i = 0; i < KD*BNT/2048; i++) {
        int f = tid + i*256;
        int k = f / (BNT/8), c = (f % (BNT/8)) * 8;
        cpa16(saddr(Bres + k*SB + c), W + (size_t)k*BNT + c);
    }
    CP_COMMIT();
    // ---- prefetch A stages 0,1 (tile 0 local) ----
    #pragma unroll
    for (int s = 0; s < 2; s++) {
        int row0 = bid * 128, k0 = s * 32;
        #pragma unroll
        for (int i = 0; i < 2; i++) {
            int f = tid + i*256, r = f >> 2, c = (f & 3) * 8;
            cpa16(saddr(&As[s][r][c]), A + (size_t)(row0+r)*KD + k0 + c);
        }
        CP_COMMIT();
    }

    int tloc = 0;
    for (int tile = bid; tile < ntiles; tile += G, tloc++) {
        int row0 = tile * 128;
        wmma::fragment<wmma::accumulator, 16,16,16, float> acc[WRN][4];
        #pragma unroll
        for (int i=0;i<WRN;i++)
            #pragma unroll
            for (int j=0;j<4;j++) wmma::fill_fragment(acc[i][j], 0.0f);

        for (int chunk = 0; chunk < NK; chunk++) {
            int s = tloc * NK + chunk;
            if (s == Slast) { CP_WAIT0(); } else { CP_WAIT1(); }
            __syncthreads();
            int cb = s % 3;
            int k0 = chunk * 32;
            #pragma unroll
            for (int kk = 0; kk < 32; kk += 16) {
                wmma::fragment<wmma::matrix_a, 16,16,16, bf16, wmma::row_major> af[WRN];
                wmma::fragment<wmma::matrix_b, 16,16,16, bf16, wmma::row_major> bfr[4];
                #pragma unroll
                for (int i=0;i<WRN;i++) wmma::load_matrix_sync(af[i], &As[cb][wr+i*16][kk], 40);
                #pragma unroll
                for (int j=0;j<4;j++)
                    wmma::load_matrix_sync(bfr[j], Bres + (k0+kk)*SB + wc + j*16, SB);
                #pragma unroll
                for (int i=0;i<WRN;i++)
                    #pragma unroll
                    for (int j=0;j<4;j++)
                        wmma::mma_sync(acc[i][j], af[i], bfr[j], acc[i][j]);
            }
            int s2 = s + 2;
            if (s2 <= Slast) {
                int t2  = bid + (s2 / NK) * G;
                int r02 = t2 * 128;
                int k02 = (s2 % NK) * 32;
                #pragma unroll
                for (int i = 0; i < 2; i++) {
                    int f = tid + i*256, r = f >> 2, c = (f & 3) * 8;
                    cpa16(saddr(&As[s2%3][r][c]), A + (size_t)(r02+r)*KD + k02 + c);
                }
                CP_COMMIT();
            }
        }

        // ---- epilogue ----
        #pragma unroll
        for (int i=0;i<WRN;i++)
            #pragma unroll
            for (int j=0;j<4;j++) {
                wmma::store_matrix_sync(&Cs[wid][0][0], acc[i][j], 20, wmma::mem_row_major);
                __syncwarp();
                int rbase = row0 + wr + i*16;
                int cbase = wc + j*16;
                #pragma unroll
                for (int e=0;e<4;e++){
                    int p  = lane*4 + e;
                    int rr = p >> 3;
                    int cc = (p & 7) * 2;
                    float v0 = Cs[wid][rr][cc]   + bias[cbase+cc];
                    float v1 = Cs[wid][rr][cc+1] + bias[cbase+cc+1];
                    if (RELU){ v0 = fmaxf(v0,0.f); v1 = fmaxf(v1,0.f); }
                    size_t off = (size_t)(rbase+rr)*BNT + cbase + cc;
                    if (ADDSRC){ v0 += Add[off]; v1 += Add[off+1]; }
                    if (OUTBF){
                        *reinterpret_cast<bf162*>(reinterpret_cast<bf16*>(Cout) + off) =
                            __float22bfloat162_rn(make_float2(v0,v1));
                    } else {
                        *reinterpret_cast<float2*>(reinterpret_cast<float*>(Cout) + off) =
                            make_float2(v0,v1);
                    }
                }
                __syncwarp();
            }
    }
}

// ======= persistent fused pos GEMM: B=fd2 resident, A ALU-generated ==========
// epilogue: pos = acc + fd2_b ; g = q - kg + pos ; vp = vg + pos  (bf16)
// smem: Bres[256][264] | As[2][128][40] | Cs[8][16][20] | misc
#define PGP_AS   135168
#define PGP_CS   (PGP_AS + 20480)
#define PGP_MISC (PGP_CS + 10240)
#define PGP_SMEM (PGP_MISC + 6656)   // 172544

__global__ void __launch_bounds__(256, 1)
posg_pk(const float* __restrict__ xyz, const float* __restrict__ xyzs,
        const float* __restrict__ fd1w, const float* __restrict__ fd1b,
        const float* __restrict__ fd2b, int ntiles)
{
    extern __shared__ __align__(16) char smem[];
    constexpr int SB = 264;
    bf16* Bres = (bf16*)smem;
    typedef bf16 (*AsT)[128][40];
    AsT As = (AsT)(smem + PGP_AS);
    float (*Cs)[16][20] = (float(*)[16][20])(smem + PGP_CS);
    int*   sQ  = (int*)(smem + PGP_MISC);
    int*   sS  = sQ + 128;
    float* sD0 = (float*)(sS + 128);
    float* sD1 = sD0 + 128;
    float* sD2 = sD1 + 128;
    float* sF0 = sD2 + 128;
    float* sF1 = sF0 + 256;
    float* sF2 = sF1 + 256;
    float* sFb = sF2 + 256;

    int bid = blockIdx.x, G = gridDim.x;
    int tid = threadIdx.x;
    int wid = tid >> 5, lane = tid & 31;
    int wr = (wid >> 2) * 64;
    int wc = (wid & 3) * 64;

    // resident B = fd2 (256x256)
    #pragma unroll
    for (int i = 0; i < 32; i++) {
        int f = tid + i*256;
        int k = f >> 5, c = (f & 31) * 8;
        cpa16(saddr(Bres + k*SB + c), g_w_fd2 + (size_t)k*DM_ + c);
    }
    CP_COMMIT();
    sF0[tid] = fd1w[tid]; sF1[tid] = fd1w[256+tid];
    sF2[tid] = fd1w[512+tid]; sFb[tid] = fd1b[tid];
    CP_WAIT0();
    __syncthreads();   // B + sF ready

    for (int tile = bid; tile < ntiles; tile += G) {
        int row0 = tile * 128;
        __syncthreads();   // protect misc from previous epilogue readers
        if (tid < 128) {
            int r = row0 + tid;
            int b = r >> 15;
            int n = (r & 32767) >> 4;
            int i = g_knn[r];
            sQ[tid] = b * N_ + n;
            sS[tid] = b * M_ + i;
            const float* x = xyz  + ((size_t)b * N_ + n) * 3;
            const float* y = xyzs + ((size_t)b * M_ + i) * 3;
            sD0[tid] = x[0]-y[0]; sD1[tid] = x[1]-y[1]; sD2[tid] = x[2]-y[2];
        }
        __syncthreads();

        // generate A chunk 0
        #pragma unroll
        for (int e = 0; e < 16; e++) {
            int f = tid + e * 256;
            int r = f & 127;
            int k = f >> 7;
            float h = fmaf(sD0[r], sF0[k],
                      fmaf(sD1[r], sF1[k],
                      fmaf(sD2[r], sF2[k], sFb[k])));
            As[0][r][k] = __float2bfloat16(fmaxf(h, 0.0f));
        }

        wmma::fragment<wmma::accumulator, 16,16,16, float> acc[4][4];
        #pragma unroll
        for (int i=0;i<4;i++)
            #pragma unroll
            for (int j=0;j<4;j++) wmma::fill_fragment(acc[i][j], 0.0f);

        for (int chunk = 0; chunk < 8; chunk++) {
            __syncthreads();   // gen(chunk) visible; old reads of target buf done
            int ab = chunk & 1;
            int k0 = chunk * 32;
            #pragma unroll
            for (int kk = 0; kk < 32; kk += 16) {
                wmma::fragment<wmma::matrix_a, 16,16,16, bf16, wmma::row_major> af[4];
                wmma::fragment<wmma::matrix_b, 16,16,16, bf16, wmma::row_major> bfr[4];
                #pragma unroll
                for (int i=0;i<4;i++) wmma::load_matrix_sync(af[i], &As[ab][wr+i*16][kk], 40);
                #pragma unroll
                for (int j=0;j<4;j++)
                    wmma::load_matrix_sync(bfr[j], Bres + (k0+kk)*SB + wc + j*16, SB);
                #pragma unroll
                for (int i=0;i<4;i++)
                    #pragma unroll
                    for (int j=0;j<4;j++)
                        wmma::mma_sync(acc[i][j], af[i], bfr[j], acc[i][j]);
            }
            if (chunk < 7) {
                int nb = (chunk+1) & 1, k0n = (chunk+1) << 5;
                #pragma unroll
                for (int e = 0; e < 16; e++) {
                    int f = tid + e * 256;
                    int r = f & 127;
                    int k = f >> 7;
                    int tc = k0n + k;
                    float h = fmaf(sD0[r], sF0[tc],
                              fmaf(sD1[r], sF1[tc],
                              fmaf(sD2[r], sF2[tc], sFb[tc])));
                    As[nb][r][k] = __float2bfloat16(fmaxf(h, 0.0f));
                }
            }
        }

        #pragma unroll
        for (int i=0;i<4;i++)
            #pragma unroll
            for (int j=0;j<4;j++) {
                wmma::store_matrix_sync(&Cs[wid][0][0], acc[i][j], 20, wmma::mem_row_major);
                __syncwarp();
                int rloc  = wr + i*16;
                int cbase = wc + j*16;
                #pragma unroll
                for (int e=0;e<4;e++){
                    int p  = lane*4 + e;
                    int rr = p >> 3;
                    int cc = (p & 7) * 2;
                    int rl = rloc + rr;
                    int r  = row0 + rl;
                    float pos0 = Cs[wid][rr][cc]   + fd2b[cbase+cc];
                    float pos1 = Cs[wid][rr][cc+1] + fd2b[cbase+cc+1];
                    size_t qoff = (size_t)sQ[rl] * DM_ + cbase + cc;
                    size_t soff = (size_t)sS[rl] * DM_ + cbase + cc;
                    float2 qv = __bfloat1622float2(*reinterpret_cast<const bf162*>(g_qb + qoff));
                    float2 kv = __bfloat1622float2(*reinterpret_cast<const bf162*>(g_kb + soff));
                    float2 vv = __bfloat1622float2(*reinterpret_cast<const bf162*>(g_vb + soff));
                    size_t off = (size_t)r * DM_ + cbase + cc;
                    *reinterpret_cast<bf162*>(g_gb + off) =
                        __float22bfloat162_rn(make_float2(qv.x - kv.x + pos0, qv.y - kv.y + pos1));
                    *reinterpret_cast<bf162*>(g_vpb + off) =
                        __float22bfloat162_rn(make_float2(vv.x + pos0, vv.y + pos1));
                }
                __syncwarp();
            }
    }
}

// ======= persistent fused a=h@fg2+b -> softmax(K) -> res reduce ==============
// B=fg2 resident; A 2-stage ring; Cs overlaid on As[1]; aS[128][256] bf16
#define ATP_AS   135168
#define ATP_CS   (ATP_AS + 10240)          // = As[1] region (overlay)
#define ATP_A2S  (ATP_AS + 20480)
#define ATP_SMEM (ATP_A2S + 65536)         // 221184

__global__ void __launch_bounds__(256, 1)
attn_pk(const bf16* __restrict__ A,          // g_hb
        const float* __restrict__ bias,      // fg2b
        float* __restrict__ attn_out, int write_attn, int ntiles)
{
    extern __shared__ __align__(16) char smem[];
    constexpr int SB = 264;
    bf16* Bres = (bf16*)smem;
    typedef bf16 (*AsT)[128][40];
    AsT As = (AsT)(smem + ATP_AS);
    float (*Cs)[16][20] = (float(*)[16][20])(smem + ATP_CS);   // overlay on As[1]
    bf16* aS = (bf16*)(smem + ATP_A2S);

    int bid = blockIdx.x, G = gridDim.x;
    int tid = threadIdx.x;
    int wid = tid >> 5, lane = tid & 31;
    int wr = (wid >> 2) * 64;
    int wc = (wid & 3) * 64;

    int nloc  = (ntiles - bid + G - 1) / G;
    int Slast = nloc * 8 - 1;

    // resident B = fg2
    #pragma unroll
    for (int i = 0; i < 32; i++) {
        int f = tid + i*256;
        int k = f >> 5, c = (f & 31) * 8;
        cpa16(saddr(Bres + k*SB + c), g_w_fg2 + (size_t)k*DM_ + c);
    }
    CP_COMMIT();
    // A stage 0
    {
        int row0 = bid * 128;
        #pragma unroll
        for (int i = 0; i < 2; i++) {
            int f = tid + i*256, r = f >> 2, c = (f & 3) * 8;
            cpa16(saddr(&As[0][r][c]), A + (size_t)(row0+r)*DM_ + c);
        }
        CP_COMMIT();
    }

    int tloc = 0;
    for (int tile = bid; tile < ntiles; tile += G, tloc++) {
        int row0 = tile * 128;
        wmma::fragment<wmma::accumulator, 16,16,16, float> acc[4][4];
        #pragma unroll
        for (int i=0;i<4;i++)
            #pragma unroll
            for (int j=0;j<4;j++) wmma::fill_fragment(acc[i][j], 0.0f);

        for (int chunk = 0; chunk < 8; chunk++) {
            int s = tloc * 8 + chunk;
            __syncthreads();            // prev compute done -> target buffer free
            if (s + 1 <= Slast) {
                int t2  = bid + ((s+1) >> 3) * G;
                int r02 = t2 * 128;
                int k02 = ((s+1) & 7) * 32;
                #pragma unroll
                for (int i = 0; i < 2; i++) {
                    int f = tid + i*256, r = f >> 2, c = (f & 3) * 8;
                    cpa16(saddr(&As[(s+1)&1][r][c]), A + (size_t)(r02+r)*DM_ + k02 + c);
                }
                CP_COMMIT();
                CP_WAIT1();
            } else {
                CP_WAIT0();
            }
            __syncthreads();            // A(s) visible to all warps
            int ab = s & 1;
            int k0 = chunk * 32;
            #pragma unroll
            for (int kk = 0; kk < 32; kk += 16) {
                wmma::fragment<wmma::matrix_a, 16,16,16, bf16, wmma::row_major> af[4];
                wmma::fragment<wmma::matrix_b, 16,16,16, bf16, wmma::row_major> bfr[4];
                #pragma unroll
                for (int i=0;i<4;i++) wmma::load_matrix_sync(af[i], &As[ab][wr+i*16][kk], 40);
                #pragma unroll
                for (int j=0;j<4;j++)
                    wmma::load_matrix_sync(bfr[j], Bres + (k0+kk)*SB + wc + j*16, SB);
                #pragma unroll
                for (int i=0;i<4;i++)
                    #pragma unroll
                    for (int j=0;j<4;j++)
                        wmma::mma_sync(acc[i][j], af[i], bfr[j], acc[i][j]);
            }
        }
        __syncthreads();   // all warps done with As[1] before Cs overlay writes

        // stage a into aS (bias added, bf16 — identical rounding to before)
        #pragma unroll
        for (int i=0;i<4;i++)
            #pragma unroll
            for (int j=0;j<4;j++) {
                wmma::store_matrix_sync(&Cs[wid][0][0], acc[i][j], 20, wmma::mem_row_major);
                __syncwarp();
                int rloc  = wr + i*16;
                int cbase = wc + j*16;
                #pragma unroll
                for (int e=0;e<4;e++){
                    int p  = lane*4 + e;
                    int rr = p >> 3;
                    int cc = (p & 7) * 2;
                    float v0 = Cs[wid][rr][cc]   + bias[cbase+cc];
                    float v1 = Cs[wid][rr][cc+1] + bias[cbase+cc+1];
                    *reinterpret_cast<bf162*>(&aS[(size_t)(rloc+rr)*256 + cbase + cc]) =
                        __float22bfloat162_rn(make_float2(v0, v1));
                }
                __syncwarp();
            }
        __syncthreads();

        // softmax over K=16 per bn group; reduce with vp
        int f = tid;
        #pragma unroll
        for (int g = 0; g < 8; g++) {
            int bn = tile * 8 + g;
            float av[K_];
            float mx = -3.4e38f;
            #pragma unroll
            for (int k = 0; k < K_; k++) {
                av[k] = __bfloat162float(aS[(size_t)(g*16+k)*256 + f]) * 0.0625f;
                mx = fmaxf(mx, av[k]);
            }
            float s = 0.0f;
            #pragma unroll
            for (int k = 0; k < K_; k++) { av[k] = expf(av[k] - mx); s += av[k]; }
            float inv = 1.0f / s;
            float res = 0.0f;
            const bf16* vpp = g_vpb + (size_t)bn * K_ * DM_ + f;
            #pragma unroll
            for (int k = 0; k < K_; k++) {
                float a = av[k] * inv;
                if (write_attn) attn_out[((size_t)bn * K_ + k) * DM_ + f] = a;
                res = fmaf(a, __bfloat162float(vpp[k*DM_]), res);
            }
            g_resb[(size_t)bn * DM_ + f] = __float2bfloat16(res);
        }
    }
}

// --------------------------------- launch ------------------------------------
extern "C" void kernel_launch(void* const* d_in, const int* in_sizes, int n_in,
                              void* d_out, int out_size)
{
    const float* xyz   = (const float*)d_in[0];
    const float* feat  = (const float*)d_in[1];
    const float* xyzs  = (const float*)d_in[2];
    const float* feats = (const float*)d_in[3];
    const float* fc1w  = (const float*)d_in[4];
    const float* fc1b  = (const float*)d_in[5];
    const float* fc1sw = (const float*)d_in[6];
    const float* fc1sb = (const float*)d_in[7];
    const float* fc2w  = (const float*)d_in[8];
    const float* fc2b  = (const float*)d_in[9];
    const float* fd1w  = (const float*)d_in[10];
    const float* fd1b  = (const float*)d_in[11];
    const float* fd2w  = (const float*)d_in[12];
    const float* fd2b  = (const float*)d_in[13];
    const float* fg1w  = (const float*)d_in[14];
    const float* fg1b  = (const float*)d_in[15];
    const float* fg2w  = (const float*)d_in[16];
    const float* fg2b  = (const float*)d_in[17];
    const float* wk    = (const float*)d_in[18];
    const float* wv    = (const float*)d_in[19];

    static bool init = false;
    static bf16 *p_featb, *p_featsb, *p_qb, *p_xsb, *p_kb, *p_vb, *p_gb, *p_hb, *p_resb;
    static bf16 *pw_fc1, *pw_fc1s, *pw_wk, *pw_wv, *pw_fd2, *pw_fg1, *pw_fg2, *pw_fc2;
    static float *p_outtmp, *p_zero;
    if (!init) {
        cudaGetSymbolAddress((void**)&p_featb,  g_featb);
        cudaGetSymbolAddress((void**)&p_featsb, g_featsb);
        cudaGetSymbolAddress((void**)&p_qb,  g_qb);
        cudaGetSymbolAddress((void**)&p_xsb, g_xsb);
        cudaGetSymbolAddress((void**)&p_kb,  g_kb);
        cudaGetSymbolAddress((void**)&p_vb,  g_vb);
        cudaGetSymbolAddress((void**)&p_gb,  g_gb);
        cudaGetSymbolAddress((void**)&p_hb,  g_hb);
        cudaGetSymbolAddress((void**)&p_resb, g_resb);
        cudaGetSymbolAddress((void**)&pw_fc1,  g_w_fc1);
        cudaGetSymbolAddress((void**)&pw_fc1s, g_w_fc1s);
        cudaGetSymbolAddress((void**)&pw_wk,   g_w_wk);
        cudaGetSymbolAddress((void**)&pw_wv,   g_w_wv);
        cudaGetSymbolAddress((void**)&pw_fd2,  g_w_fd2);
        cudaGetSymbolAddress((void**)&pw_fg1,  g_w_fg1);
        cudaGetSymbolAddress((void**)&pw_fg2,  g_w_fg2);
        cudaGetSymbolAddress((void**)&pw_fc2,  g_w_fc2);
        cudaGetSymbolAddress((void**)&p_outtmp, g_outtmp);
        cudaGetSymbolAddress((void**)&p_zero,   g_zerobias);

        cudaFuncSetAttribute(hgemm_pk<128,256,false,false,true>,
                             cudaFuncAttributeMaxDynamicSharedMemorySize, HGP_SMEM(128,256));
        cudaFuncSetAttribute(hgemm_pk<256,256,false,false,true>,
                             cudaFuncAttributeMaxDynamicSharedMemorySize, HGP_SMEM(256,256));
        cudaFuncSetAttribute(hgemm_pk<256,256,true,false,true>,
                             cudaFuncAttributeMaxDynamicSharedMemorySize, HGP_SMEM(256,256));
        cudaFuncSetAttribute(hgemm_pk<256,128,false,true,false>,
                             cudaFuncAttributeMaxDynamicSharedMemorySize, HGP_SMEM(256,128));
        cudaFuncSetAttribute(posg_pk,
                             cudaFuncAttributeMaxDynamicSharedMemorySize, PGP_SMEM);
        cudaFuncSetAttribute(attn_pk,
                             cudaFuncAttributeMaxDynamicSharedMemorySize, ATP_SMEM);
        init = true;
    }

    const long long OUTE  = (long long)BN_ * DP_;     //  2,097,152
    const long long ATTNE = (long long)BNK_ * DM_;    // 67,108,864
    float* out = (float*)d_out;
    float* out_main; float* out_attn; int write_attn;
    if ((long long)out_size >= OUTE + ATTNE) { out_main = out; out_attn = out + OUTE; write_attn = 1; }
    else if ((long long)out_size == ATTNE)   { out_main = p_outtmp; out_attn = out; write_attn = 1; }
    else                                      { out_main = out; out_attn = nullptr; write_attn = 0; }

    // 1. KNN (exact fp32)
    knn_k<<<dim3(B_, N_/128), 128>>>(xyz, xyzs);

    // 2. all fp32->bf16 conversions in ONE launch
    CvtArgs ca;
    ca.s[0]=feat;  ca.d[0]=p_featb;
    ca.s[1]=feats; ca.d[1]=p_featsb;
    ca.s[2]=fc1w;  ca.d[2]=pw_fc1;
    ca.s[3]=fc1sw; ca.d[3]=pw_fc1s;
    ca.s[4]=wk;    ca.d[4]=pw_wk;
    ca.s[5]=wv;    ca.d[5]=pw_wv;
    ca.s[6]=fd2w;  ca.d[6]=pw_fd2;
    ca.s[7]=fg1w;  ca.d[7]=pw_fg1;
    ca.s[8]=fg2w;  ca.d[8]=pw_fg2;
    ca.s[9]=fc2w;  ca.d[9]=pw_fc2;
    cvtall_k<<<CVT_BLOCKS, 256>>>(ca);

    // 3. q = feat @ fc1 + b ; xs = feats @ fc1s + b
    hgemm_pk<128,256,false,false,true><<<128, 256, HGP_SMEM(128,256)>>>(p_featb,  pw_fc1,  fc1b,  nullptr, p_qb,  BN_/128);
    hgemm_pk<128,256,false,false,true><<<128, 256, HGP_SMEM(128,256)>>>(p_featsb, pw_fc1s, fc1sb, nullptr, p_xsb, BN_/128);
    // 4. k_all = xs @ wk ; v_all = xs @ wv
    hgemm_pk<256,256,false,false,true><<<128, 256, HGP_SMEM(256,256)>>>(p_xsb, pw_wk, p_zero, nullptr, p_kb, BN_/128);
    hgemm_pk<256,256,false,false,true><<<128, 256, HGP_SMEM(256,256)>>>(p_xsb, pw_wv, p_zero, nullptr, p_vb, BN_/128);
    // 5. fused pos GEMM -> g (bf16), vp (bf16)   [persistent]
    posg_pk<<<GPD, 256, PGP_SMEM>>>(xyz, xyzs, fd1w, fd1b, fd2b, BNK_/128);
    // 6. h = relu(g @ fg1 + b)                   [persistent]
    hgemm_pk<256,256,true,false,true><<<GPD, 256, HGP_SMEM(256,256)>>>(p_gb, pw_fg1, fg1b, nullptr, p_hb, BNK_/128);
    // 7+8. a = h @ fg2 + b -> softmax(K) -> res  [persistent, fused]
    attn_pk<<<GPD, 256, ATP_SMEM>>>(p_hb, fg2b, out_attn, write_attn, BNK_/128);
    // 9. out = features + res @ fc2 + b
    hgemm_pk<256,128,false,true,false><<<128, 256, HGP_SMEM(256,128)>>>(p_resb, pw_fc2, fc2b, feat, out_main, BN_/128);
}

// round 17
// speedup vs baseline: 1.1895x; 1.1895x over previous
#include <cuda_runtime.h>
#include <cuda_bf16.h>
#include <mma.h>
#include <cstdint>
using namespace nvcuda;

#define B_  8
#define N_  2048
#define M_  2048
#define DP_ 128
#define DM_ 256
#define K_  16
#define BN_  (B_*N_)        // 16384
#define BNK_ (B_*N_*K_)     // 262144

typedef __nv_bfloat16 bf16;
typedef __nv_bfloat162 bf162;

// ---------------- scratch (device globals: allocation-free rule) -------------
__device__ bf16  g_featb [BN_*DP_];
__device__ bf16  g_featsb[BN_*DP_];
__device__ bf16  g_qb [BN_*DM_];    // qf1 = feat@Wqf + bqf
__device__ bf16  g_xsb[BN_*DM_];
__device__ bf16  g_kb [BN_*DM_];    // kf1 = xs@Wkf
__device__ bf16  g_vb [BN_*DM_];
__device__ bf16  g_resb[BN_*DM_];
__device__ float g_outtmp[BN_*DP_];
__device__ int   g_knn [BNK_];
__device__ float g_zerobias[DM_];   // zero-initialized

// bf16 weight copies
__device__ bf16 g_w_fc1s[DP_*DM_];
__device__ bf16 g_w_wv  [DM_*DM_];
__device__ bf16 g_w_fd2 [DM_*DM_];
__device__ bf16 g_w_fg2 [DM_*DM_];
__device__ bf16 g_w_fc2 [DM_*DP_];
// wprep outputs
__device__ bf16  g_w_qf [DP_*DM_];  // fc1@fg1
__device__ bf16  g_w_kf [DM_*DM_];  // wk@fg1
__device__ bf16  g_w_12 [DM_*DM_];  // fd2@fg1
__device__ float g_b_qf [DM_];      // fc1b@fg1
__device__ float g_b_12 [DM_];      // fd2b@fg1 + fg1b

// ---------------- cp.async helpers -------------------------------------------
__device__ __forceinline__ unsigned saddr(const void* p) {
    return (unsigned)__cvta_generic_to_shared(p);
}
__device__ __forceinline__ void cpa16(unsigned dst, const void* src) {
    asm volatile("cp.async.cg.shared.global [%0], [%1], 16;\n" :: "r"(dst), "l"(src));
}
#define CP_COMMIT()  asm volatile("cp.async.commit_group;\n")
#define CP_WAIT1()   asm volatile("cp.async.wait_group 1;\n")
#define CP_WAIT0()   asm volatile("cp.async.wait_group 0;\n")

// ---------------- fused fp32 -> bf16 convert ---------------------------------
struct CvtArgs { const float* s[7]; bf16* d[7]; };
#define CVT_TOTAL 4456448LL
#define CVT_BLOCKS 8704

__global__ void __launch_bounds__(256) cvtall_k(CvtArgs a)
{
    const long long cum[8] = {0LL, 2097152LL, 4194304LL, 4227072LL,
                              4292608LL, 4358144LL, 4423680LL, 4456448LL};
    long long p = ((long long)blockIdx.x * 256 + threadIdx.x) * 2;
    if (p >= CVT_TOTAL) return;
    int seg = 0;
    #pragma unroll
    for (int s = 1; s < 7; s++) if (p >= cum[s]) seg = s;
    long long off = p - cum[seg];
    float2 v = *reinterpret_cast<const float2*>(a.s[seg] + off);
    *reinterpret_cast<bf162*>(a.d[seg] + off) = __float22bfloat162_rn(v);
}

// ---------------- weight prep: folded GEMM weights (fp32 math) ---------------
// blocks: 0..127 Wqf=fc1@fg1 | 128..383 Wkf=wk@fg1 | 384..639 W12=fd2@fg1
//         640 bqf=fc1b@fg1 | 641 b12=fd2b@fg1+fg1b
__global__ void __launch_bounds__(256) wprep_k(
    const float* __restrict__ fc1w, const float* __restrict__ wkw,
    const float* __restrict__ fd2w, const float* __restrict__ fg1w,
    const float* __restrict__ fc1b, const float* __restrict__ fd2b,
    const float* __restrict__ fg1b)
{
    __shared__ float srow[DM_];
    int rb = blockIdx.x, j = threadIdx.x;
    const float* src;
    if      (rb < 128) src = fc1w + (size_t)rb * DM_;
    else if (rb < 384) src = wkw  + (size_t)(rb-128) * DM_;
    else if (rb < 640) src = fd2w + (size_t)(rb-384) * DM_;
    else if (rb == 640) src = fc1b;
    else                src = fd2b;
    srow[j] = src[j];
    __syncthreads();
    float acc = 0.0f;
    #pragma unroll 4
    for (int c = 0; c < DM_; c++) acc = fmaf(srow[c], fg1w[(size_t)c * DM_ + j], acc);
    if      (rb < 128) g_w_qf[(size_t)rb * DM_ + j]       = __float2bfloat16(acc);
    else if (rb < 384) g_w_kf[(size_t)(rb-128) * DM_ + j] = __float2bfloat16(acc);
    else if (rb < 640) g_w_12[(size_t)(rb-384) * DM_ + j] = __float2bfloat16(acc);
    else if (rb == 640) g_b_qf[j] = acc;
    else                g_b_12[j] = acc + fg1b[j];
}

// ---------------- KNN: exact expanded-form d2, stable top-16 -----------------
__global__ void __launch_bounds__(128) knn_k(const float* __restrict__ xyz,
                                             const float* __restrict__ xyzs)
{
    __shared__ float sy0[M_], sy1[M_], sy2[M_], syn[M_];
    int b = blockIdx.x;
    int n = blockIdx.y * 128 + threadIdx.x;
    const float* ys = xyzs + (size_t)b * M_ * 3;
    for (int m = threadIdx.x; m < M_; m += 128) {
        float y0 = ys[m*3+0], y1 = ys[m*3+1], y2 = ys[m*3+2];
        sy0[m] = y0; sy1[m] = y1; sy2[m] = y2;
        syn[m] = __fadd_rn(__fadd_rn(__fmul_rn(y0,y0), __fmul_rn(y1,y1)), __fmul_rn(y2,y2));
    }
    __syncthreads();

    const float* x = xyz + ((size_t)b * N_ + n) * 3;
    float x0 = x[0], x1 = x[1], x2 = x[2];
    float xn = __fadd_rn(__fadd_rn(__fmul_rn(x0,x0), __fmul_rn(x1,x1)), __fmul_rn(x2,x2));

    float bd[K_]; int bi[K_];
    #pragma unroll
    for (int k = 0; k < K_; k++) { bd[k] = 3.4e38f; bi[k] = 0; }

    for (int m = 0; m < M_; m++) {
        float dot = __fadd_rn(__fadd_rn(__fmul_rn(x0, sy0[m]), __fmul_rn(x1, sy1[m])),
                              __fmul_rn(x2, sy2[m]));
        float d2 = __fsub_rn(__fadd_rn(xn, syn[m]), __fmul_rn(2.0f, dot));
        if (d2 < bd[K_-1]) {
            int p = K_ - 1;
            while (p > 0 && bd[p-1] > d2) { bd[p] = bd[p-1]; bi[p] = bi[p-1]; p--; }
            bd[p] = d2; bi[p] = m;
        }
    }
    size_t base = ((size_t)b * N_ + n) * K_;
    #pragma unroll
    for (int k = 0; k < K_; k++) g_knn[base + k] = bi[k];
}

// ---------------- generic bf16 wmma GEMM (R14 style, 3-stage ring) -----------
// block tile 128 x BNT; BNT=256: warp 64x64 (2x4 warps); BNT=128: warp 32x64
#define HG_SMEM(BNT) (30720 + 3*32*((BNT)+8)*2 + 10240)

template<int KD, int BNT, bool RELU, bool ADDSRC, bool OUTBF>
__device__ __forceinline__ void hgemm_body(
        const bf16* __restrict__ A, int row0,
        const bf16* __restrict__ W, int wn,
        const float* __restrict__ bias,
        const float* __restrict__ Add,
        void* __restrict__ Cout, char* smem)
{
    constexpr int SB  = BNT + 8;
    constexpr int WRN = (BNT == 256) ? 4 : 2;
    typedef bf16 (*AsT)[128][40];
    AsT As = (AsT)smem;
    bf16* Bs = (bf16*)(smem + 30720);
    float (*Cs)[16][20] = (float(*)[16][20])(smem + 30720 + 3*32*SB*2);

    const int nk = KD >> 5;
    int tid = threadIdx.x;
    int wid = tid >> 5, lane = tid & 31;
    int wr = (BNT == 256) ? (wid >> 2) * 64 : (wid >> 1) * 32;
    int wc = (BNT == 256) ? (wid & 3) * 64 : (wid & 1) * 64;

    wmma::fragment<wmma::accumulator, 16,16,16, float> acc[WRN][4];
    #pragma unroll
    for (int i=0;i<WRN;i++)
        #pragma unroll
        for (int j=0;j<4;j++) wmma::fill_fragment(acc[i][j], 0.0f);

    #pragma unroll
    for (int s = 0; s < 2; s++) {
        int k0 = s << 5;
        #pragma unroll
        for (int i=0;i<2;i++){
            int f = tid + i*256, r = f >> 2, c = (f & 3) * 8;
            cpa16(saddr(&As[s][r][c]), A + (size_t)(row0+r)*KD + k0 + c);
        }
        #pragma unroll
        for (int i=0;i<BNT/64;i++){
            int f = tid + i*256;
            int r = f / (BNT/8), c = (f % (BNT/8)) * 8;
            cpa16(saddr(Bs + s*32*SB + r*SB + c), W + (size_t)(k0+r)*wn + c);
        }
        CP_COMMIT();
    }

    for (int t = 0; t < nk; t++) {
        if (t + 1 < nk) { CP_WAIT1(); } else { CP_WAIT0(); }
        __syncthreads();
        int cb = t % 3;
        #pragma unroll
        for (int kk = 0; kk < 32; kk += 16) {
            wmma::fragment<wmma::matrix_a, 16,16,16, bf16, wmma::row_major> af[WRN];
            wmma::fragment<wmma::matrix_b, 16,16,16, bf16, wmma::row_major> bfr[4];
            #pragma unroll
            for (int i=0;i<WRN;i++) wmma::load_matrix_sync(af[i], &As[cb][wr+i*16][kk], 40);
            #pragma unroll
            for (int j=0;j<4;j++)
                wmma::load_matrix_sync(bfr[j], Bs + cb*32*SB + kk*SB + wc + j*16, SB);
            #pragma unroll
            for (int i=0;i<WRN;i++)
                #pragma unroll
                for (int j=0;j<4;j++)
                    wmma::mma_sync(acc[i][j], af[i], bfr[j], acc[i][j]);
        }
        if (t + 2 < nk) {
            int nb = (t+2) % 3, k0 = (t+2) << 5;
            #pragma unroll
            for (int i=0;i<2;i++){
                int f = tid + i*256, r = f >> 2, c = (f & 3) * 8;
                cpa16(saddr(&As[nb][r][c]), A + (size_t)(row0+r)*KD + k0 + c);
            }
            #pragma unroll
            for (int i=0;i<BNT/64;i++){
                int f = tid + i*256;
                int r = f / (BNT/8), c = (f % (BNT/8)) * 8;
                cpa16(saddr(Bs + nb*32*SB + r*SB + c), W + (size_t)(k0+r)*wn + c);
            }
            CP_COMMIT();
        }
    }

    #pragma unroll
    for (int i=0;i<WRN;i++)
        #pragma unroll
        for (int j=0;j<4;j++) {
            wmma::store_matrix_sync(&Cs[wid][0][0], acc[i][j], 20, wmma::mem_row_major);
            __syncwarp();
            int rbase = row0 + wr + i*16;
            int cbase = wc + j*16;
            #pragma unroll
            for (int e=0;e<4;e++){
                int p  = lane*4 + e;
                int rr = p >> 3;
                int cc = (p & 7) * 2;
                float v0 = Cs[wid][rr][cc]   + bias[cbase+cc];
                float v1 = Cs[wid][rr][cc+1] + bias[cbase+cc+1];
                if (RELU){ v0 = fmaxf(v0,0.f); v1 = fmaxf(v1,0.f); }
                size_t off = (size_t)(rbase+rr)*wn + cbase + cc;
                if (ADDSRC){ v0 += Add[off]; v1 += Add[off+1]; }
                if (OUTBF){
                    *reinterpret_cast<bf162*>(reinterpret_cast<bf16*>(Cout) + off) =
                        __float22bfloat162_rn(make_float2(v0,v1));
                } else {
                    *reinterpret_cast<float2*>(reinterpret_cast<float*>(Cout) + off) =
                        make_float2(v0,v1);
                }
            }
            __syncwarp();
        }
}

template<int KD, int BNT, bool RELU, bool ADDSRC, bool OUTBF>
__global__ void __launch_bounds__(256, 1)
hgemm_k(const bf16* __restrict__ A, const bf16* __restrict__ W, int wn,
        const float* __restrict__ bias, const float* __restrict__ Add,
        void* __restrict__ Cout)
{
    extern __shared__ __align__(16) char smem[];
    hgemm_body<KD,BNT,RELU,ADDSRC,OUTBF>(A, blockIdx.x*128, W, wn, bias, Add, Cout, smem);
}

// two independent GEMM jobs in one launch (grid = 2*tiles)
template<int KD>
__global__ void __launch_bounds__(256, 1)
dual_k(const bf16* A0, const bf16* W0, const float* b0, bf16* C0,
       const bf16* A1, const bf16* W1, const float* b1, bf16* C1, int tiles)
{
    extern __shared__ __align__(16) char smem[];
    int bid = blockIdx.x;
    if (bid < tiles)
        hgemm_body<KD,256,false,false,true>(A0, bid*128, W0, DM_, b0, nullptr, C0, smem);
    else
        hgemm_body<KD,256,false,false,true>(A1, (bid-tiles)*128, W1, DM_, b1, nullptr, C1, smem);
}

// ================== MEGA: whole BNK pipeline in one kernel ===================
// per 128-row tile: rm = relu(delta@fd1+b) in SMEM; then
//   mainloop1 rm@fd2 -> vp = vg + pos                (vp in SMEM)
//   mainloop2 rm@W12 -> h = relu(. + qf1g - kf1g + b12)  (h overwrites rm)
//   mainloop3 h@fg2  -> logits (overwrite h), softmax over K, res reduce
// smem: SRM 128x264 bf16 | SVP 128x264 bf16 | ring 3x32x264 bf16 | Cs | misc
#define MG_SRM  0
#define MG_SVP  67584
#define MG_SB   135168
#define MG_SCS  185856
#define MG_SQ   196096
#define MG_SS   196608
#define MG_SD0  197120
#define MG_SD1  197632
#define MG_SD2  198144
#define MG_SF0  198656
#define MG_SF1  199680
#define MG_SF2  200704
#define MG_SFB  201728
#define MG_SMEM 202752

__global__ void __launch_bounds__(256, 1)
mega_k(const float* __restrict__ xyz, const float* __restrict__ xyzs,
       const float* __restrict__ fd1w, const float* __restrict__ fd1b,
       const float* __restrict__ fd2b, const float* __restrict__ fg2b,
       float* __restrict__ attn_out, int write_attn)
{
    extern __shared__ __align__(16) char smem[];
    bf16* SRM = (bf16*)(smem + MG_SRM);
    bf16* SVP = (bf16*)(smem + MG_SVP);
    bf16* Bs  = (bf16*)(smem + MG_SB);
    float (*Cs)[16][20] = (float(*)[16][20])(smem + MG_SCS);
    int*   sQ  = (int*)(smem + MG_SQ);
    int*   sS  = (int*)(smem + MG_SS);
    float* sD0 = (float*)(smem + MG_SD0);
    float* sD1 = (float*)(smem + MG_SD1);
    float* sD2 = (float*)(smem + MG_SD2);
    float* sF0 = (float*)(smem + MG_SF0);
    float* sF1 = (float*)(smem + MG_SF1);
    float* sF2 = (float*)(smem + MG_SF2);
    float* sFb = (float*)(smem + MG_SFB);

    int tile = blockIdx.x;
    int row0 = tile * 128;
    int tid = threadIdx.x, wid = tid >> 5, lane = tid & 31;
    int wr = (wid >> 2) * 64, wc = (wid & 3) * 64;

    sF0[tid] = fd1w[tid]; sF1[tid] = fd1w[256+tid];
    sF2[tid] = fd1w[512+tid]; sFb[tid] = fd1b[tid];
    if (tid < 128) {
        int r = row0 + tid;
        int b = r >> 15;
        int n = (r & 32767) >> 4;
        int i = g_knn[r];
        sQ[tid] = b * N_ + n;
        sS[tid] = b * M_ + i;
        const float* x = xyz  + ((size_t)b * N_ + n) * 3;
        const float* y = xyzs + ((size_t)b * M_ + i) * 3;
        sD0[tid] = x[0]-y[0]; sD1[tid] = x[1]-y[1]; sD2[tid] = x[2]-y[2];
    }
    __syncthreads();

    // generate rm into SRM (bf16, identical rounding to previous As tiles)
    {
        int c0 = (tid & 127) * 2;
        int r0 = (tid >> 7) * 64;
        float f00=sF0[c0], f01=sF0[c0+1], f10=sF1[c0], f11=sF1[c0+1];
        float f20=sF2[c0], f21=sF2[c0+1], fb0=sFb[c0], fb1=sFb[c0+1];
        for (int r = r0; r < r0 + 64; r++) {
            float d0=sD0[r], d1=sD1[r], d2=sD2[r];
            float h0 = fmaf(d0,f00, fmaf(d1,f10, fmaf(d2,f20, fb0)));
            float h1 = fmaf(d0,f01, fmaf(d1,f11, fmaf(d2,f21, fb1)));
            *reinterpret_cast<bf162*>(&SRM[r*264 + c0]) =
                __float22bfloat162_rn(make_float2(fmaxf(h0,0.f), fmaxf(h1,0.f)));
        }
    }
    __syncthreads();

    auto ringpf = [&](const bf16* W, int s) {
        int k0 = s << 5, buf = s % 3;
        #pragma unroll
        for (int i = 0; i < 4; i++) {
            int f = tid + i*256, r = f >> 5, c = (f & 31) * 8;
            cpa16(saddr(Bs + buf*32*264 + r*264 + c), W + (size_t)(k0+r)*DM_ + c);
        }
        CP_COMMIT();
    };

    wmma::fragment<wmma::accumulator, 16,16,16, float> acc[4][4];
    auto mainloop = [&](const bf16* W) {
        #pragma unroll
        for (int i=0;i<4;i++)
            #pragma unroll
            for (int j=0;j<4;j++) wmma::fill_fragment(acc[i][j], 0.0f);
        for (int t = 0; t < 8; t++) {
            if (t == 7) { CP_WAIT0(); } else { CP_WAIT1(); }
            __syncthreads();
            int buf = t % 3, k0 = t << 5;
            #pragma unroll
            for (int kk = 0; kk < 32; kk += 16) {
                wmma::fragment<wmma::matrix_a, 16,16,16, bf16, wmma::row_major> af[4];
                wmma::fragment<wmma::matrix_b, 16,16,16, bf16, wmma::row_major> bfr[4];
                #pragma unroll
                for (int i=0;i<4;i++)
                    wmma::load_matrix_sync(af[i], &SRM[(wr+i*16)*264 + k0 + kk], 264);
                #pragma unroll
                for (int j=0;j<4;j++)
                    wmma::load_matrix_sync(bfr[j], Bs + buf*32*264 + kk*264 + wc + j*16, 264);
                #pragma unroll
                for (int i=0;i<4;i++)
                    #pragma unroll
                    for (int j=0;j<4;j++)
                        wmma::mma_sync(acc[i][j], af[i], bfr[j], acc[i][j]);
            }
            if (t + 2 < 8) ringpf(W, t + 2);
        }
    };

    // ---------- mainloop 1: pos = rm@fd2 ;  vp = vg + pos -> SVP ----------
    ringpf(g_w_fd2, 0); ringpf(g_w_fd2, 1);
    mainloop(g_w_fd2);
    __syncthreads();
    ringpf(g_w_12, 0); ringpf(g_w_12, 1);   // overlap W12 loads with epilogue1
    #pragma unroll
    for (int i=0;i<4;i++)
        #pragma unroll
        for (int j=0;j<4;j++) {
            wmma::store_matrix_sync(&Cs[wid][0][0], acc[i][j], 20, wmma::mem_row_major);
            __syncwarp();
            int rbase = wr + i*16, cbase = wc + j*16;
            #pragma unroll
            for (int e=0;e<4;e++){
                int p = lane*4 + e, rr = p >> 3, cc = (p & 7) * 2;
                int rl = rbase + rr;
                float p0 = Cs[wid][rr][cc]   + fd2b[cbase+cc];
                float p1 = Cs[wid][rr][cc+1] + fd2b[cbase+cc+1];
                float2 vv = __bfloat1622float2(
                    *reinterpret_cast<const bf162*>(g_vb + (size_t)sS[rl]*DM_ + cbase + cc));
                *reinterpret_cast<bf162*>(&SVP[rl*264 + cbase + cc]) =
                    __float22bfloat162_rn(make_float2(vv.x + p0, vv.y + p1));
            }
            __syncwarp();
        }

    // ---------- mainloop 2: h = relu(rm@W12 + qf1g - kf1g + b12) -> SRM ----
    mainloop(g_w_12);
    __syncthreads();                         // all SRM reads done
    ringpf(g_w_fg2, 0); ringpf(g_w_fg2, 1);  // overlap fg2 loads with epilogue2
    #pragma unroll
    for (int i=0;i<4;i++)
        #pragma unroll
        for (int j=0;j<4;j++) {
            wmma::store_matrix_sync(&Cs[wid][0][0], acc[i][j], 20, wmma::mem_row_major);
            __syncwarp();
            int rbase = wr + i*16, cbase = wc + j*16;
            #pragma unroll
            for (int e=0;e<4;e++){
                int p = lane*4 + e, rr = p >> 3, cc = (p & 7) * 2;
                int rl = rbase + rr;
                float2 qv = __bfloat1622float2(
                    *reinterpret_cast<const bf162*>(g_qb + (size_t)sQ[rl]*DM_ + cbase + cc));
                float2 kv = __bfloat1622float2(
                    *reinterpret_cast<const bf162*>(g_kb + (size_t)sS[rl]*DM_ + cbase + cc));
                float h0 = Cs[wid][rr][cc]   + g_b_12[cbase+cc]   + qv.x - kv.x;
                float h1 = Cs[wid][rr][cc+1] + g_b_12[cbase+cc+1] + qv.y - kv.y;
                *reinterpret_cast<bf162*>(&SRM[rl*264 + cbase + cc]) =
                    __float22bfloat162_rn(make_float2(fmaxf(h0,0.f), fmaxf(h1,0.f)));
            }
            __syncwarp();
        }

    // ---------- mainloop 3: logits = h@fg2 + fg2b -> SRM -------------------
    mainloop(g_w_fg2);
    __syncthreads();                         // all SRM(h) reads done
    #pragma unroll
    for (int i=0;i<4;i++)
        #pragma unroll
        for (int j=0;j<4;j++) {
            wmma::store_matrix_sync(&Cs[wid][0][0], acc[i][j], 20, wmma::mem_row_major);
            __syncwarp();
            int rbase = wr + i*16, cbase = wc + j*16;
            #pragma unroll
            for (int e=0;e<4;e++){
                int p = lane*4 + e, rr = p >> 3, cc = (p & 7) * 2;
                int rl = rbase + rr;
                float a0 = Cs[wid][rr][cc]   + fg2b[cbase+cc];
                float a1 = Cs[wid][rr][cc+1] + fg2b[cbase+cc+1];
                *reinterpret_cast<bf162*>(&SRM[rl*264 + cbase + cc]) =
                    __float22bfloat162_rn(make_float2(a0, a1));
            }
            __syncwarp();
        }
    __syncthreads();

    // ---------- softmax over K=16 per bn group; reduce with vp -------------
    int f = tid;
    #pragma unroll
    for (int g = 0; g < 8; g++) {
        int bn = tile * 8 + g;
        float av[K_];
        float mx = -3.4e38f;
        #pragma unroll
        for (int k = 0; k < K_; k++) {
            av[k] = __bfloat162float(SRM[(g*16+k)*264 + f]) * 0.0625f;
            mx = fmaxf(mx, av[k]);
        }
        float s = 0.0f;
        #pragma unroll
        for (int k = 0; k < K_; k++) { av[k] = expf(av[k] - mx); s += av[k]; }
        float inv = 1.0f / s;
        float res = 0.0f;
        #pragma unroll
        for (int k = 0; k < K_; k++) {
            float a = av[k] * inv;
            if (write_attn) attn_out[((size_t)bn * K_ + k) * DM_ + f] = a;
            res = fmaf(a, __bfloat162float(SVP[(g*16+k)*264 + f]), res);
        }
        g_resb[(size_t)bn * DM_ + f] = __float2bfloat16(res);
    }
}

// --------------------------------- launch ------------------------------------
extern "C" void kernel_launch(void* const* d_in, const int* in_sizes, int n_in,
                              void* d_out, int out_size)
{
    const float* xyz   = (const float*)d_in[0];
    const float* feat  = (const float*)d_in[1];
    const float* xyzs  = (const float*)d_in[2];
    const float* feats = (const float*)d_in[3];
    const float* fc1w  = (const float*)d_in[4];
    const float* fc1b  = (const float*)d_in[5];
    const float* fc1sw = (const float*)d_in[6];
    const float* fc1sb = (const float*)d_in[7];
    const float* fc2w  = (const float*)d_in[8];
    const float* fc2b  = (const float*)d_in[9];
    const float* fd1w  = (const float*)d_in[10];
    const float* fd1b  = (const float*)d_in[11];
    const float* fd2w  = (const float*)d_in[12];
    const float* fd2b  = (const float*)d_in[13];
    const float* fg1w  = (const float*)d_in[14];
    const float* fg1b  = (const float*)d_in[15];
    const float* fg2w  = (const float*)d_in[16];
    const float* fg2b  = (const float*)d_in[17];
    const float* wk    = (const float*)d_in[18];
    const float* wv    = (const float*)d_in[19];

    static bool init = false;
    static bf16 *p_featb, *p_featsb, *p_qb, *p_xsb, *p_kb, *p_vb, *p_resb;
    static bf16 *pw_fc1s, *pw_wv, *pw_fd2, *pw_fg2, *pw_fc2, *pw_qf, *pw_kf;
    static float *p_outtmp, *p_zero, *pb_qf;
    if (!init) {
        cudaGetSymbolAddress((void**)&p_featb,  g_featb);
        cudaGetSymbolAddress((void**)&p_featsb, g_featsb);
        cudaGetSymbolAddress((void**)&p_qb,  g_qb);
        cudaGetSymbolAddress((void**)&p_xsb, g_xsb);
        cudaGetSymbolAddress((void**)&p_kb,  g_kb);
        cudaGetSymbolAddress((void**)&p_vb,  g_vb);
        cudaGetSymbolAddress((void**)&p_resb, g_resb);
        cudaGetSymbolAddress((void**)&pw_fc1s, g_w_fc1s);
        cudaGetSymbolAddress((void**)&pw_wv,   g_w_wv);
        cudaGetSymbolAddress((void**)&pw_fd2,  g_w_fd2);
        cudaGetSymbolAddress((void**)&pw_fg2,  g_w_fg2);
        cudaGetSymbolAddress((void**)&pw_fc2,  g_w_fc2);
        cudaGetSymbolAddress((void**)&pw_qf,   g_w_qf);
        cudaGetSymbolAddress((void**)&pw_kf,   g_w_kf);
        cudaGetSymbolAddress((void**)&pb_qf,   g_b_qf);
        cudaGetSymbolAddress((void**)&p_outtmp, g_outtmp);
        cudaGetSymbolAddress((void**)&p_zero,   g_zerobias);

        cudaFuncSetAttribute(dual_k<128>,
                             cudaFuncAttributeMaxDynamicSharedMemorySize, HG_SMEM(256));
        cudaFuncSetAttribute(dual_k<256>,
                             cudaFuncAttributeMaxDynamicSharedMemorySize, HG_SMEM(256));
        cudaFuncSetAttribute(hgemm_k<256,128,false,true,false>,
                             cudaFuncAttributeMaxDynamicSharedMemorySize, HG_SMEM(128));
        cudaFuncSetAttribute(mega_k,
                             cudaFuncAttributeMaxDynamicSharedMemorySize, MG_SMEM);
        init = true;
    }

    const long long OUTE  = (long long)BN_ * DP_;     //  2,097,152
    const long long ATTNE = (long long)BNK_ * DM_;    // 67,108,864
    float* out = (float*)d_out;
    float* out_main; float* out_attn; int write_attn;
    if ((long long)out_size >= OUTE + ATTNE) { out_main = out; out_attn = out + OUTE; write_attn = 1; }
    else if ((long long)out_size == ATTNE)   { out_main = p_outtmp; out_attn = out; write_attn = 1; }
    else                                      { out_main = out; out_attn = nullptr; write_attn = 0; }

    // (1) fp32->bf16 conversions
    CvtArgs ca;
    ca.s[0]=feat;  ca.d[0]=p_featb;
    ca.s[1]=feats; ca.d[1]=p_featsb;
    ca.s[2]=fc1sw; ca.d[2]=pw_fc1s;
    ca.s[3]=wv;    ca.d[3]=pw_wv;
    ca.s[4]=fd2w;  ca.d[4]=pw_fd2;
    ca.s[5]=fg2w;  ca.d[5]=pw_fg2;
    ca.s[6]=fc2w;  ca.d[6]=pw_fc2;
    cvtall_k<<<CVT_BLOCKS, 256>>>(ca);
    // (2) folded-weight prep (fp32 math)
    wprep_k<<<642, 256>>>(fc1w, wk, fd2w, fg1w, fc1b, fd2b, fg1b);
    // (3) KNN (exact fp32)
    knn_k<<<dim3(B_, N_/128), 128>>>(xyz, xyzs);
    // (4) xs = feats@fc1s + b  AND  qf1 = feat@Wqf + bqf
    dual_k<128><<<256, 256, HG_SMEM(256)>>>(p_featsb, pw_fc1s, fc1sb, p_xsb,
                                            p_featb,  pw_qf,   pb_qf, p_qb, 128);
    // (5) v_all = xs@wv  AND  kf1 = xs@Wkf
    dual_k<256><<<256, 256, HG_SMEM(256)>>>(p_xsb, pw_wv, p_zero, p_vb,
                                            p_xsb, pw_kf, p_zero, p_kb, 128);
    // (6) MEGA: rm gen -> pos/vp -> h -> logits -> softmax -> res  [PROFILED]
    mega_k<<<BNK_/128, 256, MG_SMEM>>>(xyz, xyzs, fd1w, fd1b, fd2b, fg2b,
                                       out_attn, write_attn);
    // (7) out = features + res@fc2 + b
    hgemm_k<256,128,false,true,false><<<BN_/128, 256, HG_SMEM(128)>>>(
        p_resb, pw_fc2, DP_, fc2b, feat, out_main);
}